// round 1
// baseline (speedup 1.0000x reference)
#include <cuda_runtime.h>
#include <stdint.h>

// Problem constants (fixed instance: vel[10000,1000,3] fp32, vacf_window=100)
#define T_TOTAL   10000
#define C_TOTAL   3000
#define C2_TOTAL  1500          // float2 (packed channel-pair) columns
#define W         100           // lags actually needed
#define NL        13            // lags per warp
#define NW        8             // warps per block
#define LAG_SLOTS (NL * NW)     // 104 computed lag slots (100 used)
#define TT        780           // left-operand timesteps per tile (divisible by NL)
#define R_ROWS    (TT + LAG_SLOTS)  // 884 smem rows
#define CB        32            // float2 columns per block (64 scalar channels)
#define NUM_TB    13            // ceil(10000/780)
#define NUM_CB    47            // ceil(1500/32)
#define NBLOCKS   (NUM_TB * NUM_CB)  // 611
#define SMEM_BYTES (R_ROWS * CB * 8) // 226304 B

// Per-block partial sums (written fully by every block every launch -> no init needed)
__device__ float g_partial[NBLOCKS][LAG_SLOTS];

__device__ __forceinline__ unsigned long long fma2(unsigned long long a,
                                                   unsigned long long b,
                                                   unsigned long long c) {
    unsigned long long d;
    asm("fma.rn.f32x2 %0, %1, %2, %3;" : "=l"(d) : "l"(a), "l"(b), "l"(c));
    return d;
}

extern "C" __global__ void __launch_bounds__(256, 1)
vacf_partial_kernel(const float2* __restrict__ vel) {
    extern __shared__ unsigned long long sm_u[];   // [R_ROWS][CB] as u64 (float2)
    float2* sm_f2 = reinterpret_cast<float2*>(sm_u);

    const int lane = threadIdx.x & 31;
    const int wid  = threadIdx.x >> 5;
    const int cb   = blockIdx.x;
    const int tb   = blockIdx.y;
    const int t0   = tb * TT;
    const int c2   = cb * CB + lane;
    const bool cvalid = (c2 < C2_TOTAL);

    // ---- Load tile: rows t0 .. t0+R_ROWS-1, zero beyond T or invalid channel ----
    for (int r = wid; r < R_ROWS; r += NW) {
        const int t = t0 + r;
        float2 v = make_float2(0.0f, 0.0f);
        if (t < T_TOTAL && cvalid) {
            v = vel[(size_t)t * C2_TOTAL + c2];
        }
        sm_f2[r * CB + lane] = v;
    }
    __syncthreads();

    // ---- Compute: warp 'wid' owns lags [L0, L0+NL) ----
    const int L0 = wid * NL;

    unsigned long long acc[NL];
#pragma unroll
    for (int j = 0; j < NL; ++j) acc[j] = 0ULL;

    // ring[(u + j) % NL] holds y[t0 + u + L0 + j]
    unsigned long long ring[NL];
#pragma unroll
    for (int j = 0; j < NL; ++j) ring[j] = sm_u[(L0 + j) * CB + lane];

    for (int ub = 0; ub < TT; ub += NL) {
#pragma unroll
        for (int k = 0; k < NL; ++k) {
            const int u = ub + k;
            const unsigned long long x = sm_u[u * CB + lane];
#pragma unroll
            for (int j = 0; j < NL; ++j) {
                acc[j] = fma2(x, ring[(k + j) % NL], acc[j]);
            }
            // replace the value we just consumed with y[(u+1) + L0 + (NL-1)]
            ring[k] = sm_u[(u + L0 + NL) * CB + lane];
        }
    }

    // ---- Reduce across the 32 lanes (64 channels) and store partials ----
    const int bid = tb * NUM_CB + cb;
#pragma unroll
    for (int j = 0; j < NL; ++j) {
        float lo = __uint_as_float((unsigned int)(acc[j] & 0xffffffffULL));
        float hi = __uint_as_float((unsigned int)(acc[j] >> 32));
        float v = lo + hi;
#pragma unroll
        for (int off = 16; off > 0; off >>= 1) {
            v += __shfl_xor_sync(0xffffffffu, v, off);
        }
        if (lane == 0) g_partial[bid][L0 + j] = v;
    }
}

extern "C" __global__ void vacf_reduce_kernel(float* __restrict__ out) {
    const int l = threadIdx.x;
    if (l >= W) return;
    float s = 0.0f;
    for (int b = 0; b < NBLOCKS; ++b) {
        s += g_partial[b][l];
    }
    const float denom = (float)(T_TOTAL - l) * (float)C_TOTAL;
    out[l] = s / denom;
}

extern "C" void kernel_launch(void* const* d_in, const int* in_sizes, int n_in,
                              void* d_out, int out_size) {
    const float2* vel = (const float2*)d_in[0];
    float* out = (float*)d_out;

    cudaFuncSetAttribute(vacf_partial_kernel,
                         cudaFuncAttributeMaxDynamicSharedMemorySize, SMEM_BYTES);

    dim3 grid(NUM_CB, NUM_TB);
    vacf_partial_kernel<<<grid, 256, SMEM_BYTES>>>(vel);
    vacf_reduce_kernel<<<1, 128>>>(out);
}

// round 2
// speedup vs baseline: 1.3966x; 1.3966x over previous
#include <cuda_runtime.h>
#include <stdint.h>

// Problem constants (fixed instance: vel[10000,1000,3] fp32, vacf_window=100)
#define T_TOTAL   10000
#define C_TOTAL   3000
#define C2_TOTAL  1500          // float2 (packed channel-pair) columns
#define W         100           // lags actually needed
#define NL        13            // lags per warp
#define NW        8             // warps per block
#define LAG_SLOTS (NL * NW)     // 104 computed lag slots (100 used)
#define TT        338           // left-operand timesteps per tile (13*26)
#define R_ROWS    (TT + LAG_SLOTS)  // 442 smem rows
#define CB        32            // float2 columns per block (64 scalar channels)
#define NUM_TB    30            // ceil(10000/338)
#define NUM_CB    47            // ceil(1500/32)
#define NBLOCKS   (NUM_TB * NUM_CB)  // 1410
#define SMEM_BYTES (R_ROWS * CB * 8) // 113152 B -> 2 blocks/SM

// Per-block partial sums (every block writes all its slots every launch)
__device__ float g_partial[NBLOCKS][LAG_SLOTS];

__device__ __forceinline__ unsigned long long fma2(unsigned long long a,
                                                   unsigned long long b,
                                                   unsigned long long c) {
    unsigned long long d;
    asm("fma.rn.f32x2 %0, %1, %2, %3;" : "=l"(d) : "l"(a), "l"(b), "l"(c));
    return d;
}

extern "C" __global__ void __launch_bounds__(256, 2)
vacf_partial_kernel(const float2* __restrict__ vel) {
    extern __shared__ unsigned long long sm_u[];   // [R_ROWS][CB] as u64 (float2)
    float2* sm_f2 = reinterpret_cast<float2*>(sm_u);

    const int lane = threadIdx.x & 31;
    const int wid  = threadIdx.x >> 5;
    const int cb   = blockIdx.x;
    const int tb   = blockIdx.y;
    const int t0   = tb * TT;
    const int c2   = cb * CB + lane;
    const bool cvalid = (c2 < C2_TOTAL);

    // ---- Load tile: rows t0 .. t0+R_ROWS-1, zero beyond T or invalid channel ----
    for (int r = wid; r < R_ROWS; r += NW) {
        const int t = t0 + r;
        float2 v = make_float2(0.0f, 0.0f);
        if (t < T_TOTAL && cvalid) {
            v = vel[(size_t)t * C2_TOTAL + c2];
        }
        sm_f2[r * CB + lane] = v;
    }
    __syncthreads();

    // ---- Compute: warp 'wid' owns lags [L0, L0+NL) ----
    const int L0 = wid * NL;

    unsigned long long acc[NL];
#pragma unroll
    for (int j = 0; j < NL; ++j) acc[j] = 0ULL;

    // ring[(u + j) % NL] holds y[t0 + u + L0 + j]
    unsigned long long ring[NL];
#pragma unroll
    for (int j = 0; j < NL; ++j) ring[j] = sm_u[(L0 + j) * CB + lane];

    for (int ub = 0; ub < TT; ub += NL) {
        // Prefetch all 13 x values for this outer step (independent LDS, MLP=13)
        unsigned long long xv[NL];
#pragma unroll
        for (int k = 0; k < NL; ++k) {
            xv[k] = sm_u[(ub + k) * CB + lane];
        }
#pragma unroll
        for (int k = 0; k < NL; ++k) {
#pragma unroll
            for (int j = 0; j < NL; ++j) {
                acc[j] = fma2(xv[k], ring[(k + j) % NL], acc[j]);
            }
            // replace consumed value with y[(ub+k+1) + L0 + (NL-1)]
            ring[k] = sm_u[(ub + k + L0 + NL) * CB + lane];
        }
    }

    // ---- Reduce across the 32 lanes (64 channels) and store partials ----
    const int bid = tb * NUM_CB + cb;
#pragma unroll
    for (int j = 0; j < NL; ++j) {
        float lo = __uint_as_float((unsigned int)(acc[j] & 0xffffffffULL));
        float hi = __uint_as_float((unsigned int)(acc[j] >> 32));
        float v = lo + hi;
#pragma unroll
        for (int off = 16; off > 0; off >>= 1) {
            v += __shfl_xor_sync(0xffffffffu, v, off);
        }
        if (lane == 0) g_partial[bid][L0 + j] = v;
    }
}

// One block per lag; 128 threads stride over the 1410 block-partials.
extern "C" __global__ void __launch_bounds__(128)
vacf_reduce_kernel(float* __restrict__ out) {
    __shared__ float red[4];
    const int l   = blockIdx.x;
    const int tid = threadIdx.x;
    float s = 0.0f;
    for (int b = tid; b < NBLOCKS; b += 128) {
        s += g_partial[b][l];
    }
#pragma unroll
    for (int off = 16; off > 0; off >>= 1) {
        s += __shfl_xor_sync(0xffffffffu, s, off);
    }
    if ((tid & 31) == 0) red[tid >> 5] = s;
    __syncthreads();
    if (tid == 0) {
        float v = red[0] + red[1] + red[2] + red[3];
        const float denom = (float)(T_TOTAL - l) * (float)C_TOTAL;
        out[l] = v / denom;
    }
}

extern "C" void kernel_launch(void* const* d_in, const int* in_sizes, int n_in,
                              void* d_out, int out_size) {
    const float2* vel = (const float2*)d_in[0];
    float* out = (float*)d_out;

    cudaFuncSetAttribute(vacf_partial_kernel,
                         cudaFuncAttributeMaxDynamicSharedMemorySize, SMEM_BYTES);

    dim3 grid(NUM_CB, NUM_TB);
    vacf_partial_kernel<<<grid, 256, SMEM_BYTES>>>(vel);
    vacf_reduce_kernel<<<W, 128>>>(out);
}